// round 16
// baseline (speedup 1.0000x reference)
#include <cuda_runtime.h>
#include <math_constants.h>

// Problem constants
#define NPTS   100000
#define BATCH  4096
#define TOPK   10

// Shell: points with |p|^2 >= WCUT. Affects SPEED only; correctness is
// guarded by the per-ray exact-d10 radius proof and the inline fallback.
#define WCUT   0.0992f
#define SMAXN  16384

#define GRID   148                 // one block per SM: co-residency GUARANTEED
#define BLK    256
#define NWARPS (GRID * (BLK / 32))

// ---------------------------------------------------------------------------
// Device scratch (static; no runtime allocation). All counters start 0 and
// are reset by the last block at kernel end -> clean state on every replay.
// ---------------------------------------------------------------------------
__device__ float4 g_shell[SMAXN];   // (x, y, z, |p|^2), unordered
__device__ int    g_sidx[SMAXN];    // original point index
__device__ int    g_ns   = 0;       // shell count (logical)
__device__ int    g_bar0 = 0;       // grid-barrier arrive counter
__device__ int    g_go   = 0;       // grid-barrier release flag
__device__ int    g_bar1 = 0;       // end-of-kernel reset counter

// ---------------------------------------------------------------------------
// Helpers
// ---------------------------------------------------------------------------
__device__ __forceinline__ float bump_up(float x) {
    unsigned u = __float_as_uint(x);
    if (x > 0.0f)      { u += 8; }
    else if (x < 0.0f) { if ((u & 0x7FFFFFFFu) <= 8u) return 1e-30f; u -= 8; }
    else               { return 1e-30f; }
    return __uint_as_float(u);
}

// Monotone float <-> uint32 (order-preserving incl. +/-inf)
__device__ __forceinline__ unsigned f2sort(float f) {
    unsigned u = __float_as_uint(f);
    return ((int)u < 0) ? ~u : (u | 0x80000000u);
}
__device__ __forceinline__ float sort2f(unsigned s) {
    return (s & 0x80000000u) ? __uint_as_float(s ^ 0x80000000u)
                             : __uint_as_float(~s);
}

// Sorted top-10 insert (ascending); caller guarantees t < d[9].
__device__ __forceinline__ void insert10(float t, int i, float (&d)[TOPK], int (&id)[TOPK]) {
    int pos = TOPK - 1;
#pragma unroll
    for (int s = TOPK - 1; s > 0; --s) {
        if (t < d[s - 1]) { d[s] = d[s - 1]; id[s] = id[s - 1]; pos = s - 1; }
    }
    d[pos] = t; id[pos] = i;
}

// Warp-wide exact top-10 over per-lane sorted (d, id) lists. Lane r<10 gets
// the r-th smallest unique key (f2sort(t)<<32 | idx) — exact, stable.
__device__ __forceinline__ unsigned long long warp_select10(const float (&d)[TOPK],
                                                            const int (&id)[TOPK]) {
    int h = 0;
    unsigned long long cur =
        ((unsigned long long)f2sort(d[0]) << 32) | (unsigned)id[0];
    unsigned long long sel = 0xFFFFFFFFFFFFFFFFull;
#pragma unroll
    for (int r = 0; r < TOPK; ++r) {
        unsigned long long k = cur;
#pragma unroll
        for (int off = 16; off > 0; off >>= 1) {
            unsigned long long o = __shfl_xor_sync(0xFFFFFFFFu, k, off);
            k = o < k ? o : k;
        }
        if ((threadIdx.x & 31) == r) sel = k;
        if (cur == k) {
            ++h;
            cur = (h < TOPK)
                ? (((unsigned long long)f2sort(d[h]) << 32) | (unsigned)id[h])
                : 0xFFFFFFFFFFFFFFFFull;
        }
    }
    return sel;
}

// Warp epilogue: lanes 0..9 hold selected keys; writes out[ray].
__device__ __forceinline__ void epilogue(unsigned long long sel, int lane, float c2,
                                         const float* __restrict__ features_dc,
                                         const float* __restrict__ opacity,
                                         float* __restrict__ out, int ray) {
    float w = 0.f, wr = 0.f, wg = 0.f, wb = 0.f;
    if (lane < TOPK) {
        const int   k    = (int)(unsigned)sel;
        const float tv   = sort2f((unsigned)(sel >> 32));
        const float sq   = fmaxf(tv + c2, 0.0f);
        const float dist = sqrtf(sq);
        const float op   = 1.0f / (1.0f + expf(-opacity[k]));
        w  = expf(-0.1f * dist) * op;
        wr = w * (1.0f / (1.0f + expf(-features_dc[3 * k + 0])));
        wg = w * (1.0f / (1.0f + expf(-features_dc[3 * k + 1])));
        wb = w * (1.0f / (1.0f + expf(-features_dc[3 * k + 2])));
    }
#pragma unroll
    for (int off = 16; off > 0; off >>= 1) {
        w  += __shfl_xor_sync(0xFFFFFFFFu, w,  off);
        wr += __shfl_xor_sync(0xFFFFFFFFu, wr, off);
        wg += __shfl_xor_sync(0xFFFFFFFFu, wg, off);
        wb += __shfl_xor_sync(0xFFFFFFFFu, wb, off);
    }
    if (lane == 0) {
        const float inv = 1.0f / (w + 1e-8f);
        out[3 * ray + 0] = wr * inv;
        out[3 * ray + 1] = wg * inv;
        out[3 * ray + 2] = wb * inv;
    }
}

// ---------------------------------------------------------------------------
// THE kernel: phase 1 builds the shell, grid barrier, phase 2 solves rays.
// ---------------------------------------------------------------------------
__global__ void __launch_bounds__(BLK)
splat_kernel(const float* __restrict__ xyz,
             const float* __restrict__ rays_o, const float* __restrict__ rays_d,
             const float* __restrict__ features_dc, const float* __restrict__ opacity,
             float* __restrict__ out) {
    const int tid  = threadIdx.x;
    const int lane = tid & 31;
    const int warp = tid >> 5;

    // ---------------- phase 1: build shell (ballot-aggregated appends) -----
    // BLOCK-UNIFORM trip count: 'base' is identical across the block, so every
    // warp executes the same iterations with all 32 lanes present at each
    // __ballot_sync (the R12 hang was a per-lane break before a full-mask sync).
    for (int base = blockIdx.x * BLK; base < NPTS; base += GRID * BLK) {
        const int i = base + tid;
        float x = 0.f, y = 0.f, z = 0.f, w = -1.0f;
        const bool valid = (i < NPTS);
        if (valid) {
            x = xyz[3 * i + 0]; y = xyz[3 * i + 1]; z = xyz[3 * i + 2];
            w = fmaf(x, x, fmaf(y, y, z * z));   // canonical |p|^2 chain
        }
        const bool q = valid && (w >= WCUT);
        const unsigned mask = __ballot_sync(0xFFFFFFFFu, q);
        if (mask != 0u) {
            const int n = __popc(mask);
            const int leader = __ffs(mask) - 1;
            int pbase = 0;
            if (lane == leader) pbase = atomicAdd(&g_ns, n);
            pbase = __shfl_sync(0xFFFFFFFFu, pbase, leader);
            if (q) {
                const int pos = pbase + __popc(mask & ((1u << lane) - 1u));
                if (pos < SMAXN) {
                    g_shell[pos] = make_float4(x, y, z, w);
                    g_sidx[pos]  = i;
                }
            }
        }
    }

    // ---------------- grid barrier (all 148 blocks are co-resident) --------
    __syncthreads();
    if (tid == 0) {
        __threadfence();
        const int old = atomicAdd(&g_bar0, 1);
        if (old == GRID - 1) {
            __threadfence();
            *((volatile int*)&g_go) = 1;
        } else {
            while (*((volatile int*)&g_go) == 0) { __nanosleep(64); }
        }
    }
    __syncthreads();
    __threadfence();

    const int  ns_raw   = *((volatile int*)&g_ns);
    const int  ns       = ns_raw < SMAXN ? ns_raw : SMAXN;
    const bool shell_ok = (ns_raw <= SMAXN);

    // ---------------- phase 2: warp per ray --------------------------------
    const int gwarp = blockIdx.x * (BLK / 32) + warp;
    for (int ray = gwarp; ray < BATCH; ray += NWARPS) {
        const float cx = fmaf(3.0f, rays_d[3 * ray + 0], rays_o[3 * ray + 0]);
        const float cy = fmaf(3.0f, rays_d[3 * ray + 1], rays_o[3 * ray + 1]);
        const float cz = fmaf(3.0f, rays_d[3 * ray + 2], rays_o[3 * ray + 2]);
        const float mx = -2.0f * cx, my = -2.0f * cy, mz = -2.0f * cz;
        const float c2 = fmaf(cx, cx, fmaf(cy, cy, cz * cz));

        // pass 1: per-lane min over the shell -> gating tau (sound)
        float amin = CUDART_INF_F;
#pragma unroll 4
        for (int i = lane; i < ns; i += 32) {
            float4 p = g_shell[i];
            float t = fmaf(p.x, mx, fmaf(p.y, my, fmaf(p.z, mz, p.w)));
            amin = fminf(amin, t);
        }
        float v = amin, tenth = CUDART_INF_F;
#pragma unroll
        for (int r = 0; r < TOPK; ++r) {
            float m = v;
#pragma unroll
            for (int off = 16; off > 0; off >>= 1)
                m = fminf(m, __shfl_xor_sync(0xFFFFFFFFu, m, off));
            if (r == TOPK - 1) tenth = m;
            if (v == m) v = CUDART_INF_F;
        }
        const float tau = bump_up(tenth);   // > exact shell 10th

        // pass 2: tau-gated EXACT top-10 of the shell
        float d[TOPK];
        int   id[TOPK];
#pragma unroll
        for (int j = 0; j < TOPK; ++j) { d[j] = CUDART_INF_F; id[j] = 0; }

#pragma unroll 4
        for (int i = lane; i < ns; i += 32) {
            float4 p = g_shell[i];
            float t = fmaf(p.x, mx, fmaf(p.y, my, fmaf(p.z, mz, p.w)));
            if (t < tau) {
                if (t < d[TOPK - 1]) insert10(t, g_sidx[i], d, id);
            }
        }

        unsigned long long sel = warp_select10(d, id);

        // radius proof with the EXACT shell 10th distance (tighter than tau):
        // any point with dist <= d10 has |p| >= |c| - d10 = rlo; if
        // rlo^2 (guarded) >= WCUT it is in the shell -> shell top-10 is the
        // global top-10.
        const unsigned long long k9 = __shfl_sync(0xFFFFFFFFu, sel, TOPK - 1);
        const unsigned t9bits = (unsigned)(k9 >> 32);
        bool ok = shell_ok && (t9bits != 0xFFFFFFFFu);   // 10 real candidates
        const float t10   = sort2f(t9bits);
        const float cnorm = sqrtf(c2);
        const float d10   = sqrtf(fmaxf(c2 + t10, 0.0f));
        const float rlo   = cnorm - d10;
        const float rlosq = (rlo > 0.0f) ? rlo * rlo * (1.0f - 1e-4f) - 1e-7f : -1.0f;
        ok = ok && (rlosq >= WCUT);

        if (!ok) {
            // inline fallback: full exact scan gated by tau (sound: every true
            // top-10 t <= t10_full <= t10_shell < tau). Identical chains.
#pragma unroll
            for (int j = 0; j < TOPK; ++j) { d[j] = CUDART_INF_F; id[j] = 0; }
            for (int i = lane; i < NPTS; i += 32) {
                float x = xyz[3 * i + 0], y = xyz[3 * i + 1], z = xyz[3 * i + 2];
                float w = fmaf(x, x, fmaf(y, y, z * z));
                float t = fmaf(x, mx, fmaf(y, my, fmaf(z, mz, w)));
                if (t < tau && t < d[TOPK - 1]) insert10(t, i, d, id);
            }
            sel = warp_select10(d, id);
        }

        epilogue(sel, lane, c2, features_dc, opacity, out, ray);
    }

    // ---------------- end: last block resets state for the next replay -----
    __syncthreads();
    if (tid == 0) {
        __threadfence();
        const int old = atomicAdd(&g_bar1, 1);
        if (old == GRID - 1) {
            g_ns   = 0;
            g_bar0 = 0;
            g_go   = 0;
            g_bar1 = 0;
            __threadfence();
        }
    }
}

// ---------------------------------------------------------------------------
// Launch: ONE kernel node.
// ---------------------------------------------------------------------------
extern "C" void kernel_launch(void* const* d_in, const int* in_sizes, int n_in,
                              void* d_out, int out_size) {
    const float* rays_o      = (const float*)d_in[0];
    const float* rays_d      = (const float*)d_in[1];
    const float* xyz         = (const float*)d_in[2];
    const float* features_dc = (const float*)d_in[3];
    const float* opacity     = (const float*)d_in[4];
    float* out = (float*)d_out;

    splat_kernel<<<GRID, BLK>>>(xyz, rays_o, rays_d, features_dc, opacity, out);
}

// round 17
// speedup vs baseline: 7.4533x; 7.4533x over previous
#include <cuda_runtime.h>
#include <math_constants.h>

// Problem constants
#define NPTS   100000
#define BATCH  4096
#define TOPK   10

// Shell: points with |p|^2 >= WCUT (|p| >= 0.25). ~10k points expected for
// the benchmark distribution; proof needs rlo >= 0.25, typical rlo ~0.32,
// so deferrals are rare. Affects SPEED only; correctness is guarded by the
// per-ray exact-d10 radius proof and the sliced overflow phases.
#define WCUT   0.0625f
#define SMAXN  32768

#define GRID   592                 // 4 blocks/SM; launch_bounds caps regs so
#define BLK    256                 // wave-1 co-residency (barrier) is safe
#define NWARPS (GRID * (BLK / 32)) // 4736

// Overflow slicing
#define NSLICE    64
#define SLICE_PTS 1563             // ceil(NPTS / NSLICE)

// ---------------------------------------------------------------------------
// Device scratch (static). Counters start 0; last block resets them at the
// end so every graph replay starts clean.
// ---------------------------------------------------------------------------
__device__ float4 g_shell[SMAXN];
__device__ int    g_sidx[SMAXN];
__device__ int    g_ns = 0;
__device__ int    g_over_cnt = 0;
__device__ int    g_over_ray[BATCH];
__device__ float  g_over_tau[BATCH];
__device__ unsigned long long g_part[BATCH * NSLICE * TOPK];
__device__ int    g_barc[4] = {0, 0, 0, 0};   // barrier arrive counters
__device__ int    g_barg[3] = {0, 0, 0};      // barrier release flags

// ---------------------------------------------------------------------------
// Helpers
// ---------------------------------------------------------------------------
__device__ __forceinline__ float bump_up(float x) {
    unsigned u = __float_as_uint(x);
    if (x > 0.0f)      { u += 8; }
    else if (x < 0.0f) { if ((u & 0x7FFFFFFFu) <= 8u) return 1e-30f; u -= 8; }
    else               { return 1e-30f; }
    return __uint_as_float(u);
}

__device__ __forceinline__ unsigned f2sort(float f) {
    unsigned u = __float_as_uint(f);
    return ((int)u < 0) ? ~u : (u | 0x80000000u);
}
__device__ __forceinline__ float sort2f(unsigned s) {
    return (s & 0x80000000u) ? __uint_as_float(s ^ 0x80000000u)
                             : __uint_as_float(~s);
}

__device__ __forceinline__ void insert10(float t, int i, float (&d)[TOPK], int (&id)[TOPK]) {
    int pos = TOPK - 1;
#pragma unroll
    for (int s = TOPK - 1; s > 0; --s) {
        if (t < d[s - 1]) { d[s] = d[s - 1]; id[s] = id[s - 1]; pos = s - 1; }
    }
    d[pos] = t; id[pos] = i;
}

__device__ __forceinline__ void insert10_u64(unsigned long long k,
                                             unsigned long long (&dk)[TOPK]) {
    int pos = TOPK - 1;
#pragma unroll
    for (int s = TOPK - 1; s > 0; --s) {
        if (k < dk[s - 1]) { dk[s] = dk[s - 1]; pos = s - 1; }
    }
    dk[pos] = k;
}

// Warp-wide exact top-10 over per-lane sorted (d, id) lists; unique keys
// (f2sort(t)<<32 | idx) -> exact, stable (lowest idx on ties).
__device__ __forceinline__ unsigned long long warp_select10(const float (&d)[TOPK],
                                                            const int (&id)[TOPK]) {
    int h = 0;
    unsigned long long cur =
        ((unsigned long long)f2sort(d[0]) << 32) | (unsigned)id[0];
    unsigned long long sel = 0xFFFFFFFFFFFFFFFFull;
#pragma unroll
    for (int r = 0; r < TOPK; ++r) {
        unsigned long long k = cur;
#pragma unroll
        for (int off = 16; off > 0; off >>= 1) {
            unsigned long long o = __shfl_xor_sync(0xFFFFFFFFu, k, off);
            k = o < k ? o : k;
        }
        if ((threadIdx.x & 31) == r) sel = k;
        if (cur == k) {
            ++h;
            cur = (h < TOPK)
                ? (((unsigned long long)f2sort(d[h]) << 32) | (unsigned)id[h])
                : 0xFFFFFFFFFFFFFFFFull;
        }
    }
    return sel;
}

__device__ __forceinline__ unsigned long long warp_select10_u64(
        const unsigned long long (&dk)[TOPK]) {
    int h = 0;
    unsigned long long cur = dk[0];
    unsigned long long sel = 0xFFFFFFFFFFFFFFFFull;
#pragma unroll
    for (int r = 0; r < TOPK; ++r) {
        unsigned long long k = cur;
#pragma unroll
        for (int off = 16; off > 0; off >>= 1) {
            unsigned long long o = __shfl_xor_sync(0xFFFFFFFFu, k, off);
            k = o < k ? o : k;
        }
        if ((threadIdx.x & 31) == r) sel = k;
        if (cur == k) {
            ++h;
            cur = (h < TOPK) ? dk[h] : 0xFFFFFFFFFFFFFFFFull;
        }
    }
    return sel;
}

__device__ __forceinline__ void epilogue(unsigned long long sel, int lane, float c2,
                                         const float* __restrict__ features_dc,
                                         const float* __restrict__ opacity,
                                         float* __restrict__ out, int ray) {
    float w = 0.f, wr = 0.f, wg = 0.f, wb = 0.f;
    if (lane < TOPK) {
        const int   k    = (int)(unsigned)sel;
        const float tv   = sort2f((unsigned)(sel >> 32));
        const float sq   = fmaxf(tv + c2, 0.0f);
        const float dist = sqrtf(sq);
        const float op   = 1.0f / (1.0f + expf(-opacity[k]));
        w  = expf(-0.1f * dist) * op;
        wr = w * (1.0f / (1.0f + expf(-features_dc[3 * k + 0])));
        wg = w * (1.0f / (1.0f + expf(-features_dc[3 * k + 1])));
        wb = w * (1.0f / (1.0f + expf(-features_dc[3 * k + 2])));
    }
#pragma unroll
    for (int off = 16; off > 0; off >>= 1) {
        w  += __shfl_xor_sync(0xFFFFFFFFu, w,  off);
        wr += __shfl_xor_sync(0xFFFFFFFFu, wr, off);
        wg += __shfl_xor_sync(0xFFFFFFFFu, wg, off);
        wb += __shfl_xor_sync(0xFFFFFFFFu, wb, off);
    }
    if (lane == 0) {
        const float inv = 1.0f / (w + 1e-8f);
        out[3 * ray + 0] = wr * inv;
        out[3 * ray + 1] = wg * inv;
        out[3 * ray + 2] = wb * inv;
    }
}

// Grid barrier (all GRID blocks co-resident by construction).
__device__ __forceinline__ void grid_barrier(int which) {
    __syncthreads();
    if (threadIdx.x == 0) {
        __threadfence();
        const int old = atomicAdd(&g_barc[which], 1);
        if (old == GRID - 1) {
            __threadfence();
            *((volatile int*)&g_barg[which]) = 1;
        } else {
            while (*((volatile int*)&g_barg[which]) == 0) { __nanosleep(64); }
        }
    }
    __syncthreads();
    __threadfence();
}

// ---------------------------------------------------------------------------
// THE kernel
// ---------------------------------------------------------------------------
__global__ void __launch_bounds__(BLK, 4)
splat_kernel(const float* __restrict__ xyz,
             const float* __restrict__ rays_o, const float* __restrict__ rays_d,
             const float* __restrict__ features_dc, const float* __restrict__ opacity,
             float* __restrict__ out) {
    const int tid   = threadIdx.x;
    const int lane  = tid & 31;
    const int warp  = tid >> 5;
    const int gwarp = blockIdx.x * (BLK / 32) + warp;

    // ---------- phase 1: build shell (block-uniform trip count) ------------
    for (int base = blockIdx.x * BLK; base < NPTS; base += GRID * BLK) {
        const int i = base + tid;
        float x = 0.f, y = 0.f, z = 0.f, w = -1.0f;
        const bool valid = (i < NPTS);
        if (valid) {
            x = xyz[3 * i + 0]; y = xyz[3 * i + 1]; z = xyz[3 * i + 2];
            w = fmaf(x, x, fmaf(y, y, z * z));   // canonical |p|^2 chain
        }
        const bool q = valid && (w >= WCUT);
        const unsigned mask = __ballot_sync(0xFFFFFFFFu, q);
        if (mask != 0u) {
            const int n = __popc(mask);
            const int leader = __ffs(mask) - 1;
            int pbase = 0;
            if (lane == leader) pbase = atomicAdd(&g_ns, n);
            pbase = __shfl_sync(0xFFFFFFFFu, pbase, leader);
            if (q) {
                const int pos = pbase + __popc(mask & ((1u << lane) - 1u));
                if (pos < SMAXN) {
                    g_shell[pos] = make_float4(x, y, z, w);
                    g_sidx[pos]  = i;
                }
            }
        }
    }

    grid_barrier(0);

    const int  ns_raw   = *((volatile int*)&g_ns);
    const int  ns       = ns_raw < SMAXN ? ns_raw : SMAXN;
    const bool shell_ok = (ns_raw <= SMAXN);

    // ---------- phase 2: warp per ray (4736 warps >= 4096 rays) ------------
    if (gwarp < BATCH) {
        const int ray = gwarp;
        const float cx = fmaf(3.0f, rays_d[3 * ray + 0], rays_o[3 * ray + 0]);
        const float cy = fmaf(3.0f, rays_d[3 * ray + 1], rays_o[3 * ray + 1]);
        const float cz = fmaf(3.0f, rays_d[3 * ray + 2], rays_o[3 * ray + 2]);
        const float mx = -2.0f * cx, my = -2.0f * cy, mz = -2.0f * cz;
        const float c2 = fmaf(cx, cx, fmaf(cy, cy, cz * cz));

        // pass 1: per-lane min -> gating tau (sound: shell 10th >= exact 10th)
        float amin = CUDART_INF_F;
#pragma unroll 4
        for (int i = lane; i < ns; i += 32) {
            float4 p = g_shell[i];
            float t = fmaf(p.x, mx, fmaf(p.y, my, fmaf(p.z, mz, p.w)));
            amin = fminf(amin, t);
        }
        float v = amin, tenth = CUDART_INF_F;
#pragma unroll
        for (int r = 0; r < TOPK; ++r) {
            float m = v;
#pragma unroll
            for (int off = 16; off > 0; off >>= 1)
                m = fminf(m, __shfl_xor_sync(0xFFFFFFFFu, m, off));
            if (r == TOPK - 1) tenth = m;
            if (v == m) v = CUDART_INF_F;
        }
        const float tau = isinf(tenth) ? CUDART_INF_F : bump_up(tenth);

        // pass 2: tau-gated EXACT top-10 of the shell
        float d[TOPK];
        int   id[TOPK];
#pragma unroll
        for (int j = 0; j < TOPK; ++j) { d[j] = CUDART_INF_F; id[j] = 0; }
#pragma unroll 4
        for (int i = lane; i < ns; i += 32) {
            float4 p = g_shell[i];
            float t = fmaf(p.x, mx, fmaf(p.y, my, fmaf(p.z, mz, p.w)));
            if (t < tau) {
                if (t < d[TOPK - 1]) insert10(t, g_sidx[i], d, id);
            }
        }
        unsigned long long sel = warp_select10(d, id);

        // radius proof with the EXACT shell d10: any point with dist <= d10
        // has |p| >= |c| - d10; if that (guarded) >= sqrt(WCUT) it's in the
        // shell -> shell top-10 == global top-10.
        const unsigned long long k9 = __shfl_sync(0xFFFFFFFFu, sel, TOPK - 1);
        const unsigned t9bits = (unsigned)(k9 >> 32);
        bool ok = shell_ok && (t9bits != 0xFFFFFFFFu);
        const float t10   = sort2f(t9bits);
        const float cnorm = sqrtf(c2);
        const float d10   = sqrtf(fmaxf(c2 + t10, 0.0f));
        const float rlo   = cnorm - d10;
        const float rlosq = (rlo > 0.0f) ? rlo * rlo * (1.0f - 1e-4f) - 1e-7f : -1.0f;
        ok = ok && (rlosq >= WCUT);

        if (ok) {
            epilogue(sel, lane, c2, features_dc, opacity, out, ray);
        } else {
            if (lane == 0) {
                const int s = atomicAdd(&g_over_cnt, 1);
                g_over_ray[s] = ray;
                g_over_tau[s] = tau;
            }
        }
    }

    grid_barrier(1);

    // ---------- phase 3: sliced overflow partials (warp per unit) ----------
    const int nover = *((volatile int*)&g_over_cnt);
    for (int unit = gwarp; unit < nover * NSLICE; unit += NWARPS) {
        const int slot  = unit >> 6;            // / NSLICE
        const int slice = unit & (NSLICE - 1);
        const int   ray = g_over_ray[slot];
        const float tau = g_over_tau[slot];

        const float cx = fmaf(3.0f, rays_d[3 * ray + 0], rays_o[3 * ray + 0]);
        const float cy = fmaf(3.0f, rays_d[3 * ray + 1], rays_o[3 * ray + 1]);
        const float cz = fmaf(3.0f, rays_d[3 * ray + 2], rays_o[3 * ray + 2]);
        const float mx = -2.0f * cx, my = -2.0f * cy, mz = -2.0f * cz;

        const int i0 = slice * SLICE_PTS;
        const int i1 = (i0 + SLICE_PTS < NPTS) ? i0 + SLICE_PTS : NPTS;

        float d[TOPK];
        int   id[TOPK];
#pragma unroll
        for (int j = 0; j < TOPK; ++j) { d[j] = CUDART_INF_F; id[j] = 0; }

#pragma unroll 4
        for (int i = i0 + lane; i < i1; i += 32) {
            const float x = xyz[3 * i + 0], y = xyz[3 * i + 1], z = xyz[3 * i + 2];
            const float w = fmaf(x, x, fmaf(y, y, z * z));
            const float t = fmaf(x, mx, fmaf(y, my, fmaf(z, mz, w)));
            if (t < tau && t < d[TOPK - 1]) insert10(t, i, d, id);
        }

        const unsigned long long sel = warp_select10(d, id);
        if (lane < TOPK) g_part[unit * TOPK + lane] = sel;
    }

    grid_barrier(2);

    // ---------- phase 4: merge slices (warp per deferred ray) --------------
    for (int slot = gwarp; slot < nover; slot += NWARPS) {
        const int ray = g_over_ray[slot];

        unsigned long long dk[TOPK];
#pragma unroll
        for (int j = 0; j < TOPK; ++j) dk[j] = 0xFFFFFFFFFFFFFFFFull;

        const unsigned long long* __restrict__ part = g_part + slot * (NSLICE * TOPK);
#pragma unroll 4
        for (int j = 0; j < 20; ++j) {          // 640 keys, 20 per lane
            const unsigned long long k = part[lane * 20 + j];
            if (k < dk[TOPK - 1]) insert10_u64(k, dk);
        }
        const unsigned long long sel = warp_select10_u64(dk);

        const float cx = fmaf(3.0f, rays_d[3 * ray + 0], rays_o[3 * ray + 0]);
        const float cy = fmaf(3.0f, rays_d[3 * ray + 1], rays_o[3 * ray + 1]);
        const float cz = fmaf(3.0f, rays_d[3 * ray + 2], rays_o[3 * ray + 2]);
        const float c2 = fmaf(cx, cx, fmaf(cy, cy, cz * cz));
        epilogue(sel, lane, c2, features_dc, opacity, out, ray);
    }

    // ---------- end: last block resets all state for the next replay -------
    __syncthreads();
    if (tid == 0) {
        __threadfence();
        const int old = atomicAdd(&g_barc[3], 1);
        if (old == GRID - 1) {
            g_ns = 0; g_over_cnt = 0;
            g_barc[0] = 0; g_barc[1] = 0; g_barc[2] = 0; g_barc[3] = 0;
            g_barg[0] = 0; g_barg[1] = 0; g_barg[2] = 0;
            __threadfence();
        }
    }
}

// ---------------------------------------------------------------------------
// Launch: ONE kernel node.
// ---------------------------------------------------------------------------
extern "C" void kernel_launch(void* const* d_in, const int* in_sizes, int n_in,
                              void* d_out, int out_size) {
    const float* rays_o      = (const float*)d_in[0];
    const float* rays_d      = (const float*)d_in[1];
    const float* xyz         = (const float*)d_in[2];
    const float* features_dc = (const float*)d_in[3];
    const float* opacity     = (const float*)d_in[4];
    float* out = (float*)d_out;

    splat_kernel<<<GRID, BLK>>>(xyz, rays_o, rays_d, features_dc, opacity, out);
}